// round 4
// baseline (speedup 1.0000x reference)
#include <cuda_runtime.h>
#include <cuda_fp16.h>
#include <math.h>
#include <stdint.h>

#define NT 16384
#define NE 16384
#define BETA 0.25f

#define RS 200                    // halves per padded row (192 data + 8 pad)
#define RB 400                    // bytes per row
#define TILE_BYTES (128 * RB)     // 51200
#define CHUNKS (TILE_BYTES / 16)  // 3200

// ---------------- static device scratch ----------------
__device__ __half g_zf[16384 * RS];   // A' = [h_z | l_z | h_z], padded rows
__device__ __half g_ef[16384 * RS];   // B' = [h_E | h_E | l_E], E = 4096*e
__device__ float g_enorm[NE];
__device__ float g_znorm[NT];
__device__ int   g_idx[NT];
__device__ int   g_counts[NE];
__device__ float g_loss;

// ---------------- helpers ----------------
__device__ __forceinline__ uint32_t smem_u32(const void* p) {
    uint32_t a;
    asm("{ .reg .u64 t; cvta.to.shared.u64 t, %1; cvt.u32.u64 %0, t; }" : "=r"(a) : "l"(p));
    return a;
}
__device__ __forceinline__ void split2h(float v, __half& h, __half& l) {
    __half hh = __float2half_rn(v);
    float r = __fsub_rn(v, __half2float(hh));   // exact
    h = hh; l = __float2half_rn(r);
}

#define CP_ASYNC16(dst_u32, src_ptr) \
    asm volatile("cp.async.cg.shared.global [%0], [%1], 16;\n" :: "r"(dst_u32), "l"(src_ptr))
#define CP_COMMIT()  asm volatile("cp.async.commit_group;\n" ::: "memory")
#define CP_WAIT0()   asm volatile("cp.async.wait_group 0;\n" ::: "memory")

#define LDSM_X4(r, addr) \
    asm volatile("ldmatrix.sync.aligned.m8n8.x4.shared.b16 {%0,%1,%2,%3}, [%4];" \
        : "=r"((r)[0]), "=r"((r)[1]), "=r"((r)[2]), "=r"((r)[3]) : "r"(addr))
#define LDSM_X2(r, addr) \
    asm volatile("ldmatrix.sync.aligned.m8n8.x2.shared.b16 {%0,%1}, [%2];" \
        : "=r"((r)[0]), "=r"((r)[1]) : "r"(addr))

__device__ __forceinline__ void mma16816(float* c, const uint32_t* a, const uint32_t* b) {
    asm volatile(
        "mma.sync.aligned.m16n8k16.row.col.f32.f16.f16.f32 "
        "{%0,%1,%2,%3}, {%4,%5,%6,%7}, {%8,%9}, {%0,%1,%2,%3};"
        : "+f"(c[0]), "+f"(c[1]), "+f"(c[2]), "+f"(c[3])
        : "r"(a[0]), "r"(a[1]), "r"(a[2]), "r"(a[3]), "r"(b[0]), "r"(b[1]));
}

// ---------------- prep (fused): split z and E=4096*e; norms; zero counts ----------------
__global__ void k_split(const float* __restrict__ z, const float* __restrict__ emb) {
    extern __shared__ __half st[];          // 128 * RS halves = 51200 B
    int blk = blockIdx.x;                   // 0..127 z tiles, 128..255 e subtiles
    int tid = threadIdx.x;                  // 256
    if (blk < 128) {
        int tile = blk;
        int b = tile >> 3, hw0 = (tile & 7) << 7;
        for (int idx = tid; idx < 8192; idx += 256) {
            int k = idx >> 7, tl = idx & 127;
            float v = z[((size_t)(b * 64 + k) << 10) + hw0 + tl];
            __half h, l; split2h(v, h, l);
            st[tl * RS + k]       = h;
            st[tl * RS + 64 + k]  = l;
            st[tl * RS + 128 + k] = h;
        }
        __syncthreads();
        float4* dst = (float4*)(g_zf + (size_t)tile * 128 * RS);
        const float4* src = (const float4*)st;
        for (int i = tid; i < CHUNKS; i += 256) dst[i] = src[i];
        if (tid < 128) {
            float s = 0.f;
            for (int k = 0; k < 64; k++) {
                float v = z[((size_t)(b * 64 + k) << 10) + hw0 + tid];
                s += v * v;
            }
            g_znorm[(tile << 7) + tid] = s;
        }
        if (tile == 0 && tid == 0) g_loss = 0.f;
    } else {
        int sub = blk - 128;
        int n0 = sub << 7;
        for (int idx = tid; idx < 8192; idx += 256) {
            int nl = idx >> 6, k = idx & 63;
            float v = emb[(size_t)(n0 + nl) * 64 + k] * 4096.0f;   // exact scale
            __half h, l; split2h(v, h, l);
            st[nl * RS + k]       = h;
            st[nl * RS + 64 + k]  = h;
            st[nl * RS + 128 + k] = l;
        }
        __syncthreads();
        float4* dst = (float4*)(g_ef + (size_t)sub * 128 * RS);
        const float4* src = (const float4*)st;
        for (int i = tid; i < CHUNKS; i += 256) dst[i] = src[i];
        if (tid < 128) {
            float s = 0.f;
            for (int k = 0; k < 64; k++) {
                float v = emb[(size_t)(n0 + tid) * 64 + k];
                s += v * v;
            }
            g_enorm[n0 + tid] = s;
            g_counts[n0 + tid] = 0;
        }
    }
}

// ---------------- main: fp16 mma.sync distance GEMM + pipelined fused argmin ----------------
// smem: A [0,51200) | B0 [51200,102400) | B1 [102400,153600)
#define SM_TOT (3 * TILE_BYTES)

__global__ void __launch_bounds__(256, 1) k_mma(float* __restrict__ out) {
    extern __shared__ __align__(16) unsigned char sm[];
    uint32_t sb = smem_u32(sm);
    const uint32_t SA = sb, SB0 = sb + TILE_BYTES, SB1 = sb + 2 * TILE_BYTES;

    int tid = threadIdx.x, lane = tid & 31, wid = tid >> 5;
    int mw = wid & 1, nw = wid >> 1;        // 2 x 4 warp grid
    int mbase = mw * 64, nbw = nw * 32;     // warp tile 64 x 32

    // prolog: A tile + B subtile 0 (linear copies, rows pre-padded in gmem)
    {
        const char* gz = (const char*)(g_zf + (size_t)blockIdx.x * 128 * RS);
        for (int i = tid; i < CHUNKS; i += 256) CP_ASYNC16(SA + i * 16, gz + i * 16);
        const char* ge = (const char*)g_ef;
        for (int i = tid; i < CHUNKS; i += 256) CP_ASYNC16(SB0 + i * 16, ge + i * 16);
        CP_COMMIT(); CP_WAIT0();
    }
    __syncthreads();

    // per-thread rows: r = mbase + mi*16 + rh*8 + (lane>>2)
    float zn[8];
#pragma unroll
    for (int mi = 0; mi < 4; mi++)
#pragma unroll
        for (int rh = 0; rh < 2; rh++)
            zn[mi * 2 + rh] = g_znorm[(blockIdx.x << 7) + mbase + mi * 16 + rh * 8 + (lane >> 2)];

    float bv[8]; int bi[8];
#pragma unroll
    for (int r = 0; r < 8; r++) { bv[r] = 3.0e38f; bi[r] = 0; }

    // ldmatrix base addresses (conflict-free with 400B row stride)
    uint32_t a_base = SA + (uint32_t)(mbase + (lane & 15)) * RB + ((lane >> 4) & 1) * 16;
    uint32_t b_roff = (uint32_t)(nbw + (lane & 7)) * RB + ((lane >> 3) & 1) * 16;

    // double-buffered accumulators: epilogue of subtile j-1 overlaps mma of subtile j
    float acc[2][4][4][4];

    for (int j = 0; j < 128; j++) {
        int cur = j & 1;
        uint32_t Bcur  = cur ? SB1 : SB0;
        uint32_t Bnext = cur ? SB0 : SB1;

        if (j < 127) {   // prefetch next B, overlapped with this subtile's mma
            const char* src = (const char*)(g_ef + (size_t)(j + 1) * 128 * RS);
            for (int i = tid; i < CHUNKS; i += 256) CP_ASYNC16(Bnext + i * 16, src + i * 16);
            CP_COMMIT();
        }

        // en for the DEFERRED epilogue (subtile j-1); latency hidden under mma issue
        float en[8];
        if (j > 0) {
#pragma unroll
            for (int ni = 0; ni < 4; ni++) {
                int c0 = nbw + ni * 8 + (lane & 3) * 2;
                en[ni * 2]     = __ldg(&g_enorm[((j - 1) << 7) + c0]);
                en[ni * 2 + 1] = __ldg(&g_enorm[((j - 1) << 7) + c0 + 1]);
            }
        }

#pragma unroll
        for (int mi = 0; mi < 4; mi++)
#pragma unroll
            for (int ni = 0; ni < 4; ni++)
#pragma unroll
                for (int q = 0; q < 4; q++) acc[cur][mi][ni][q] = 0.f;

        uint32_t b_base = Bcur + b_roff;
#pragma unroll
        for (int ks = 0; ks < 12; ks++) {
            uint32_t a[4][4], b[4][2];
#pragma unroll
            for (int mi = 0; mi < 4; mi++)
                LDSM_X4(a[mi], a_base + mi * 16 * RB + ks * 32);
#pragma unroll
            for (int ni = 0; ni < 4; ni++)
                LDSM_X2(b[ni], b_base + ni * 8 * RB + ks * 32);
#pragma unroll
            for (int mi = 0; mi < 4; mi++)
#pragma unroll
                for (int ni = 0; ni < 4; ni++)
                    mma16816(acc[cur][mi][ni], a[mi], b[ni]);
        }

        // deferred epilogue for subtile j-1: reads acc[1-cur] — register-independent
        // of the mma stream above, so it interleaves into HMMA issue gaps.
        if (j > 0) {
            int prev = 1 - cur;
#pragma unroll
            for (int mi = 0; mi < 4; mi++) {
#pragma unroll
                for (int ni = 0; ni < 4; ni++) {
                    int n0 = ((j - 1) << 7) + nbw + ni * 8 + (lane & 3) * 2;
                    float d0 = __fsub_rn(__fadd_rn(zn[mi * 2],     en[ni * 2]),     acc[prev][mi][ni][0] * 0x1p-11f);
                    float d1 = __fsub_rn(__fadd_rn(zn[mi * 2],     en[ni * 2 + 1]), acc[prev][mi][ni][1] * 0x1p-11f);
                    float d2 = __fsub_rn(__fadd_rn(zn[mi * 2 + 1], en[ni * 2]),     acc[prev][mi][ni][2] * 0x1p-11f);
                    float d3 = __fsub_rn(__fadd_rn(zn[mi * 2 + 1], en[ni * 2 + 1]), acc[prev][mi][ni][3] * 0x1p-11f);
                    if (d0 < bv[mi * 2])     { bv[mi * 2]     = d0; bi[mi * 2]     = n0; }
                    if (d1 < bv[mi * 2])     { bv[mi * 2]     = d1; bi[mi * 2]     = n0 + 1; }
                    if (d2 < bv[mi * 2 + 1]) { bv[mi * 2 + 1] = d2; bi[mi * 2 + 1] = n0; }
                    if (d3 < bv[mi * 2 + 1]) { bv[mi * 2 + 1] = d3; bi[mi * 2 + 1] = n0 + 1; }
                }
            }
        }

        CP_WAIT0();
        __syncthreads();
    }

    // drain: epilogue for subtile 127 (acc buffer 1)
    {
        float en[8];
#pragma unroll
        for (int ni = 0; ni < 4; ni++) {
            int c0 = nbw + ni * 8 + (lane & 3) * 2;
            en[ni * 2]     = __ldg(&g_enorm[(127 << 7) + c0]);
            en[ni * 2 + 1] = __ldg(&g_enorm[(127 << 7) + c0 + 1]);
        }
#pragma unroll
        for (int mi = 0; mi < 4; mi++) {
#pragma unroll
            for (int ni = 0; ni < 4; ni++) {
                int n0 = (127 << 7) + nbw + ni * 8 + (lane & 3) * 2;
                float d0 = __fsub_rn(__fadd_rn(zn[mi * 2],     en[ni * 2]),     acc[1][mi][ni][0] * 0x1p-11f);
                float d1 = __fsub_rn(__fadd_rn(zn[mi * 2],     en[ni * 2 + 1]), acc[1][mi][ni][1] * 0x1p-11f);
                float d2 = __fsub_rn(__fadd_rn(zn[mi * 2 + 1], en[ni * 2]),     acc[1][mi][ni][2] * 0x1p-11f);
                float d3 = __fsub_rn(__fadd_rn(zn[mi * 2 + 1], en[ni * 2 + 1]), acc[1][mi][ni][3] * 0x1p-11f);
                if (d0 < bv[mi * 2])     { bv[mi * 2]     = d0; bi[mi * 2]     = n0; }
                if (d1 < bv[mi * 2])     { bv[mi * 2]     = d1; bi[mi * 2]     = n0 + 1; }
                if (d2 < bv[mi * 2 + 1]) { bv[mi * 2 + 1] = d2; bi[mi * 2 + 1] = n0; }
                if (d3 < bv[mi * 2 + 1]) { bv[mi * 2 + 1] = d3; bi[mi * 2 + 1] = n0 + 1; }
            }
        }
    }

    // quad reduce (cols within warp): lanes differing in (lane&3)
#pragma unroll
    for (int r = 0; r < 8; r++) {
#pragma unroll
        for (int off = 1; off <= 2; off <<= 1) {
            float ov = __shfl_xor_sync(0xffffffffu, bv[r], off);
            int   oi = __shfl_xor_sync(0xffffffffu, bi[r], off);
            if (ov < bv[r] || (ov == bv[r] && oi < bi[r])) { bv[r] = ov; bi[r] = oi; }
        }
    }
    __syncthreads();
    float* rv = (float*)(sm + TILE_BYTES);          // reuse B0: 128 rows x 4 nwarps
    int*   ri = (int*)(sm + TILE_BYTES + 2048);
    if ((lane & 3) == 0) {
#pragma unroll
        for (int r = 0; r < 8; r++) {
            int row = mbase + (r >> 1) * 16 + (r & 1) * 8 + (lane >> 2);
            rv[row * 4 + nw] = bv[r];
            ri[row * 4 + nw] = bi[r];
        }
    }
    __syncthreads();
    if (tid < 128) {
        float v = rv[tid * 4]; int ii = ri[tid * 4];
#pragma unroll
        for (int x = 1; x < 4; x++) {
            float ov = rv[tid * 4 + x]; int oi = ri[tid * 4 + x];
            if (ov < v || (ov == v && oi < ii)) { v = ov; ii = oi; }
        }
        int t = (blockIdx.x << 7) + tid;
        g_idx[t] = ii;
        out[1048579 + t] = (float)ii;
        atomicAdd(&g_counts[ii], 1);
    }
}

// ---------------- z_q gather + loss accumulation ----------------
__global__ void k_zq(const float* __restrict__ z, const float* __restrict__ emb,
                     float* __restrict__ out) {
    int p = blockIdx.x;            // 1024 planes = (b,c)
    int b = p >> 6, c = p & 63;
    int tid = threadIdx.x;         // 256
    float ls = 0.f;
    for (int hw = tid; hw < 1024; hw += 256) {
        int t = (b << 10) + hw;
        int id = g_idx[t];
        float v  = emb[(size_t)id * 64 + c];
        float zv = z[(size_t)p * 1024 + hw];
        out[(size_t)p * 1024 + hw] = v;
        float df = v - zv;
        ls += df * df;
    }
    __shared__ float red[8];
    for (int o = 16; o > 0; o >>= 1) ls += __shfl_down_sync(0xffffffff, ls, o);
    if ((tid & 31) == 0) red[tid >> 5] = ls;
    __syncthreads();
    if (tid == 0) {
        float s = 0.f;
        for (int w = 0; w < 8; w++) s += red[w];
        atomicAdd(&g_loss, s);
    }
}

// ---------------- scalars ----------------
__global__ void k_final(float* __restrict__ out) {
    int tid = threadIdx.x;   // 256
    float ent = 0.f; int cu = 0;
    for (int n = tid; n < NE; n += 256) {
        int c = g_counts[n];
        if (c > 0) cu++;
        float avg = (float)c * (1.0f / 16384.0f);
        ent += avg * logf(avg + 1e-10f);
    }
    __shared__ float se[256]; __shared__ int sc[256];
    se[tid] = ent; sc[tid] = cu;
    __syncthreads();
    for (int o = 128; o > 0; o >>= 1) {
        if (tid < o) { se[tid] += se[tid + o]; sc[tid] += sc[tid + o]; }
        __syncthreads();
    }
    if (tid == 0) {
        out[1048576] = g_loss * (1.0f + BETA) / 1048576.0f;
        out[1048577] = expf(-se[0]);
        out[1048578] = (float)sc[0];
    }
}

// ---------------- launch ----------------
extern "C" void kernel_launch(void* const* d_in, const int* in_sizes, int n_in,
                              void* d_out, int out_size) {
    const float* z   = (const float*)d_in[0];   // (16,64,32,32)
    const float* emb = (const float*)d_in[1];   // (16384,64)
    float* out = (float*)d_out;

    cudaFuncSetAttribute(k_split, cudaFuncAttributeMaxDynamicSharedMemorySize, TILE_BYTES);
    cudaFuncSetAttribute(k_mma,   cudaFuncAttributeMaxDynamicSharedMemorySize, SM_TOT);

    k_split<<<256, 256, TILE_BYTES>>>(z, emb);
    k_mma<<<128, 256, SM_TOT>>>(out);
    k_zq<<<1024, 256>>>(z, emb, out);
    k_final<<<1, 256>>>(out);
}

// round 5
// speedup vs baseline: 1.4096x; 1.4096x over previous
#include <cuda_runtime.h>
#include <cuda_fp16.h>
#include <math.h>
#include <stdint.h>

#define NT 16384
#define NE 16384
#define BETA 0.25f

#define RS 200                    // halves per padded row (192 data + 8 pad)
#define RB 400                    // bytes per row
#define TILE_BYTES (128 * RB)     // 51200
#define CHUNKS (TILE_BYTES / 16)  // 3200

// ---------------- static device scratch ----------------
__device__ __half g_zf[16384 * RS];   // A' = [h_z | l_z | h_z], padded rows
__device__ __half g_ef[16384 * RS];   // B' = [h_E | h_E | l_E], E = 4096*e
__device__ float g_enorm[NE];
__device__ float g_znorm[NT];
__device__ int   g_idx[NT];
__device__ int   g_counts[NE];
__device__ float g_loss;

// ---------------- helpers ----------------
__device__ __forceinline__ uint32_t smem_u32(const void* p) {
    uint32_t a;
    asm("{ .reg .u64 t; cvta.to.shared.u64 t, %1; cvt.u32.u64 %0, t; }" : "=r"(a) : "l"(p));
    return a;
}
__device__ __forceinline__ void split2h(float v, __half& h, __half& l) {
    __half hh = __float2half_rn(v);
    float r = __fsub_rn(v, __half2float(hh));   // exact
    h = hh; l = __float2half_rn(r);
}

#define CP_ASYNC16(dst_u32, src_ptr) \
    asm volatile("cp.async.cg.shared.global [%0], [%1], 16;\n" :: "r"(dst_u32), "l"(src_ptr))
#define CP_COMMIT()  asm volatile("cp.async.commit_group;\n" ::: "memory")
#define CP_WAIT0()   asm volatile("cp.async.wait_group 0;\n" ::: "memory")

#define LDSM_X4(r, addr) \
    asm volatile("ldmatrix.sync.aligned.m8n8.x4.shared.b16 {%0,%1,%2,%3}, [%4];" \
        : "=r"((r)[0]), "=r"((r)[1]), "=r"((r)[2]), "=r"((r)[3]) : "r"(addr))
#define LDSM_X2(r, addr) \
    asm volatile("ldmatrix.sync.aligned.m8n8.x2.shared.b16 {%0,%1}, [%2];" \
        : "=r"((r)[0]), "=r"((r)[1]) : "r"(addr))

__device__ __forceinline__ void mma16816(float* c, const uint32_t* a, const uint32_t* b) {
    asm volatile(
        "mma.sync.aligned.m16n8k16.row.col.f32.f16.f16.f32 "
        "{%0,%1,%2,%3}, {%4,%5,%6,%7}, {%8,%9}, {%0,%1,%2,%3};"
        : "+f"(c[0]), "+f"(c[1]), "+f"(c[2]), "+f"(c[3])
        : "r"(a[0]), "r"(a[1]), "r"(a[2]), "r"(a[3]), "r"(b[0]), "r"(b[1]));
}

// ---------------- prep (fused): split z and E=4096*e; norms; zero counts ----------------
__global__ void k_split(const float* __restrict__ z, const float* __restrict__ emb) {
    extern __shared__ __half st[];          // 128 * RS halves = 51200 B
    int blk = blockIdx.x;                   // 0..127 z tiles, 128..255 e subtiles
    int tid = threadIdx.x;                  // 256
    if (blk < 128) {
        int tile = blk;
        int b = tile >> 3, hw0 = (tile & 7) << 7;
        for (int idx = tid; idx < 8192; idx += 256) {
            int k = idx >> 7, tl = idx & 127;
            float v = z[((size_t)(b * 64 + k) << 10) + hw0 + tl];
            __half h, l; split2h(v, h, l);
            st[tl * RS + k]       = h;
            st[tl * RS + 64 + k]  = l;
            st[tl * RS + 128 + k] = h;
        }
        __syncthreads();
        float4* dst = (float4*)(g_zf + (size_t)tile * 128 * RS);
        const float4* src = (const float4*)st;
        for (int i = tid; i < CHUNKS; i += 256) dst[i] = src[i];
        if (tid < 128) {
            float s = 0.f;
            for (int k = 0; k < 64; k++) {
                float v = z[((size_t)(b * 64 + k) << 10) + hw0 + tid];
                s += v * v;
            }
            g_znorm[(tile << 7) + tid] = s;
        }
        if (tile == 0 && tid == 0) g_loss = 0.f;
    } else {
        int sub = blk - 128;
        int n0 = sub << 7;
        for (int idx = tid; idx < 8192; idx += 256) {
            int nl = idx >> 6, k = idx & 63;
            float v = emb[(size_t)(n0 + nl) * 64 + k] * 4096.0f;   // exact scale
            __half h, l; split2h(v, h, l);
            st[nl * RS + k]       = h;
            st[nl * RS + 64 + k]  = h;
            st[nl * RS + 128 + k] = l;
        }
        __syncthreads();
        float4* dst = (float4*)(g_ef + (size_t)sub * 128 * RS);
        const float4* src = (const float4*)st;
        for (int i = tid; i < CHUNKS; i += 256) dst[i] = src[i];
        if (tid < 128) {
            float s = 0.f;
            for (int k = 0; k < 64; k++) {
                float v = emb[(size_t)(n0 + tid) * 64 + k];
                s += v * v;
            }
            g_enorm[n0 + tid] = s;
            g_counts[n0 + tid] = 0;
        }
    }
}

// ---------------- main kernel building blocks (all force-inlined, static indices) ----
__device__ __forceinline__ void load_en(int j, int nbw, int lane, float en[8]) {
#pragma unroll
    for (int ni = 0; ni < 4; ni++) {
        int c0 = nbw + ni * 8 + (lane & 3) * 2;
        en[ni * 2]     = __ldg(&g_enorm[(j << 7) + c0]);
        en[ni * 2 + 1] = __ldg(&g_enorm[(j << 7) + c0 + 1]);
    }
}

__device__ __forceinline__ void mma_phase(uint32_t a_base, uint32_t b_base,
                                          float acc[4][4][4]) {
#pragma unroll
    for (int mi = 0; mi < 4; mi++)
#pragma unroll
        for (int ni = 0; ni < 4; ni++)
#pragma unroll
            for (int q = 0; q < 4; q++) acc[mi][ni][q] = 0.f;
#pragma unroll
    for (int ks = 0; ks < 12; ks++) {
        uint32_t a[4][4], b[4][2];
#pragma unroll
        for (int mi = 0; mi < 4; mi++)
            LDSM_X4(a[mi], a_base + mi * 16 * RB + ks * 32);
#pragma unroll
        for (int ni = 0; ni < 4; ni++)
            LDSM_X2(b[ni], b_base + ni * 8 * RB + ks * 32);
#pragma unroll
        for (int mi = 0; mi < 4; mi++)
#pragma unroll
            for (int ni = 0; ni < 4; ni++)
                mma16816(acc[mi][ni], a[mi], b[ni]);
    }
}

// d = fl( fl(zn+en) - acc*2^-11 ), single FFMA rounding (acc*2^-11 exact).
__device__ __forceinline__ void epi_phase(const float acc[4][4][4], const float en[8],
                                          const float zn[8], int j, int nbw, int lane,
                                          float bv[8], int bi[8]) {
#pragma unroll
    for (int mi = 0; mi < 4; mi++) {
#pragma unroll
        for (int ni = 0; ni < 4; ni++) {
            int n0 = (j << 7) + nbw + ni * 8 + (lane & 3) * 2;
            float c00 = __fadd_rn(zn[mi * 2],     en[ni * 2]);
            float c01 = __fadd_rn(zn[mi * 2],     en[ni * 2 + 1]);
            float c10 = __fadd_rn(zn[mi * 2 + 1], en[ni * 2]);
            float c11 = __fadd_rn(zn[mi * 2 + 1], en[ni * 2 + 1]);
            float d0 = fmaf(acc[mi][ni][0], -0x1p-11f, c00);
            float d1 = fmaf(acc[mi][ni][1], -0x1p-11f, c01);
            float d2 = fmaf(acc[mi][ni][2], -0x1p-11f, c10);
            float d3 = fmaf(acc[mi][ni][3], -0x1p-11f, c11);
            if (d0 < bv[mi * 2])     { bv[mi * 2]     = d0; bi[mi * 2]     = n0; }
            if (d1 < bv[mi * 2])     { bv[mi * 2]     = d1; bi[mi * 2]     = n0 + 1; }
            if (d2 < bv[mi * 2 + 1]) { bv[mi * 2 + 1] = d2; bi[mi * 2 + 1] = n0; }
            if (d3 < bv[mi * 2 + 1]) { bv[mi * 2 + 1] = d3; bi[mi * 2 + 1] = n0 + 1; }
        }
    }
}

// ---------------- main: fp16 mma.sync distance GEMM + pipelined fused argmin ----------------
// smem: A [0,51200) | B0 [51200,102400) | B1 [102400,153600)
#define SM_TOT (3 * TILE_BYTES)

__global__ void __launch_bounds__(256, 1) k_mma(float* __restrict__ out) {
    extern __shared__ __align__(16) unsigned char sm[];
    uint32_t sb = smem_u32(sm);
    const uint32_t SA = sb, SB0 = sb + TILE_BYTES, SB1 = sb + 2 * TILE_BYTES;

    int tid = threadIdx.x, lane = tid & 31, wid = tid >> 5;
    int mw = wid & 1, nw = wid >> 1;        // 2 x 4 warp grid
    int mbase = mw * 64, nbw = nw * 32;     // warp tile 64 x 32

    // prolog: A tile + B subtile 0 (linear copies, rows pre-padded in gmem)
    {
        const char* gz = (const char*)(g_zf + (size_t)blockIdx.x * 128 * RS);
        for (int i = tid; i < CHUNKS; i += 256) CP_ASYNC16(SA + i * 16, gz + i * 16);
        const char* ge = (const char*)g_ef;
        for (int i = tid; i < CHUNKS; i += 256) CP_ASYNC16(SB0 + i * 16, ge + i * 16);
        CP_COMMIT(); CP_WAIT0();
    }
    __syncthreads();

    // per-thread rows: r = mbase + mi*16 + rh*8 + (lane>>2)
    float zn[8];
#pragma unroll
    for (int mi = 0; mi < 4; mi++)
#pragma unroll
        for (int rh = 0; rh < 2; rh++)
            zn[mi * 2 + rh] = g_znorm[(blockIdx.x << 7) + mbase + mi * 16 + rh * 8 + (lane >> 2)];

    float bv[8]; int bi[8];
#pragma unroll
    for (int r = 0; r < 8; r++) { bv[r] = 3.0e38f; bi[r] = 0; }

    // ldmatrix base addresses (conflict-free with 400B row stride)
    uint32_t a_base = SA + (uint32_t)(mbase + (lane & 15)) * RB + ((lane >> 4) & 1) * 16;
    uint32_t b_roff = (uint32_t)(nbw + (lane & 7)) * RB + ((lane >> 3) & 1) * 16;

    // statically named accumulator buffers — compile-time phase selection,
    // so both stay in registers (dynamic indexing would demote to local mem).
    float acc0[4][4][4], acc1[4][4][4];

    for (int jj = 0; jj < 128; jj += 2) {
        // ---- phase A: subtile jj (B in SB0, fills acc0, epilogues acc1 = subtile jj-1)
        {
            const char* src = (const char*)(g_ef + (size_t)(jj + 1) * 128 * RS);
            for (int i = tid; i < CHUNKS; i += 256) CP_ASYNC16(SB1 + i * 16, src + i * 16);
            CP_COMMIT();

            float en[8];
            if (jj > 0) load_en(jj - 1, nbw, lane, en);
            mma_phase(a_base, SB0 + b_roff, acc0);
            if (jj > 0) epi_phase(acc1, en, zn, jj - 1, nbw, lane, bv, bi);

            CP_WAIT0();
            __syncthreads();
        }
        // ---- phase B: subtile jj+1 (B in SB1, fills acc1, epilogues acc0 = subtile jj)
        {
            if (jj + 2 < 128) {
                const char* src = (const char*)(g_ef + (size_t)(jj + 2) * 128 * RS);
                for (int i = tid; i < CHUNKS; i += 256) CP_ASYNC16(SB0 + i * 16, src + i * 16);
                CP_COMMIT();
            }

            float en[8];
            load_en(jj, nbw, lane, en);
            mma_phase(a_base, SB1 + b_roff, acc1);
            epi_phase(acc0, en, zn, jj, nbw, lane, bv, bi);

            CP_WAIT0();
            __syncthreads();
        }
    }

    // drain: epilogue for subtile 127 (acc1)
    {
        float en[8];
        load_en(127, nbw, lane, en);
        epi_phase(acc1, en, zn, 127, nbw, lane, bv, bi);
    }

    // quad reduce (cols within warp): lanes differing in (lane&3)
#pragma unroll
    for (int r = 0; r < 8; r++) {
#pragma unroll
        for (int off = 1; off <= 2; off <<= 1) {
            float ov = __shfl_xor_sync(0xffffffffu, bv[r], off);
            int   oi = __shfl_xor_sync(0xffffffffu, bi[r], off);
            if (ov < bv[r] || (ov == bv[r] && oi < bi[r])) { bv[r] = ov; bi[r] = oi; }
        }
    }
    __syncthreads();
    float* rv = (float*)(sm + TILE_BYTES);          // reuse B0: 128 rows x 4 nwarps
    int*   ri = (int*)(sm + TILE_BYTES + 2048);
    if ((lane & 3) == 0) {
#pragma unroll
        for (int r = 0; r < 8; r++) {
            int row = mbase + (r >> 1) * 16 + (r & 1) * 8 + (lane >> 2);
            rv[row * 4 + nw] = bv[r];
            ri[row * 4 + nw] = bi[r];
        }
    }
    __syncthreads();
    if (tid < 128) {
        float v = rv[tid * 4]; int ii = ri[tid * 4];
#pragma unroll
        for (int x = 1; x < 4; x++) {
            float ov = rv[tid * 4 + x]; int oi = ri[tid * 4 + x];
            if (ov < v || (ov == v && oi < ii)) { v = ov; ii = oi; }
        }
        int t = (blockIdx.x << 7) + tid;
        g_idx[t] = ii;
        out[1048579 + t] = (float)ii;
        atomicAdd(&g_counts[ii], 1);
    }
}

// ---------------- z_q gather + loss accumulation ----------------
__global__ void k_zq(const float* __restrict__ z, const float* __restrict__ emb,
                     float* __restrict__ out) {
    int p = blockIdx.x;            // 1024 planes = (b,c)
    int b = p >> 6, c = p & 63;
    int tid = threadIdx.x;         // 256
    float ls = 0.f;
    for (int hw = tid; hw < 1024; hw += 256) {
        int t = (b << 10) + hw;
        int id = g_idx[t];
        float v  = emb[(size_t)id * 64 + c];
        float zv = z[(size_t)p * 1024 + hw];
        out[(size_t)p * 1024 + hw] = v;
        float df = v - zv;
        ls += df * df;
    }
    __shared__ float red[8];
    for (int o = 16; o > 0; o >>= 1) ls += __shfl_down_sync(0xffffffff, ls, o);
    if ((tid & 31) == 0) red[tid >> 5] = ls;
    __syncthreads();
    if (tid == 0) {
        float s = 0.f;
        for (int w = 0; w < 8; w++) s += red[w];
        atomicAdd(&g_loss, s);
    }
}

// ---------------- scalars ----------------
__global__ void k_final(float* __restrict__ out) {
    int tid = threadIdx.x;   // 1024
    float ent = 0.f; int cu = 0;
    for (int n = tid; n < NE; n += 1024) {
        int c = g_counts[n];
        if (c > 0) cu++;
        float avg = (float)c * (1.0f / 16384.0f);
        ent += avg * logf(avg + 1e-10f);
    }
    __shared__ float se[1024]; __shared__ int sc[1024];
    se[tid] = ent; sc[tid] = cu;
    __syncthreads();
    for (int o = 512; o > 0; o >>= 1) {
        if (tid < o) { se[tid] += se[tid + o]; sc[tid] += sc[tid + o]; }
        __syncthreads();
    }
    if (tid == 0) {
        out[1048576] = g_loss * (1.0f + BETA) / 1048576.0f;
        out[1048577] = expf(-se[0]);
        out[1048578] = (float)sc[0];
    }
}

// ---------------- launch ----------------
extern "C" void kernel_launch(void* const* d_in, const int* in_sizes, int n_in,
                              void* d_out, int out_size) {
    const float* z   = (const float*)d_in[0];   // (16,64,32,32)
    const float* emb = (const float*)d_in[1];   // (16384,64)
    float* out = (float*)d_out;

    cudaFuncSetAttribute(k_split, cudaFuncAttributeMaxDynamicSharedMemorySize, TILE_BYTES);
    cudaFuncSetAttribute(k_mma,   cudaFuncAttributeMaxDynamicSharedMemorySize, SM_TOT);

    k_split<<<256, 256, TILE_BYTES>>>(z, emb);
    k_mma<<<128, 256, SM_TOT>>>(out);
    k_zq<<<1024, 256>>>(z, emb, out);
    k_final<<<1, 1024>>>(out);
}

// round 6
// speedup vs baseline: 1.5718x; 1.1150x over previous
#include <cuda_runtime.h>
#include <cuda_fp16.h>
#include <math.h>
#include <stdint.h>

#define NT 16384
#define NE 16384
#define BETA 0.25f

#define RS2 136                     // halves per padded row (128 data + 8 pad)
#define RB2 272                     // bytes per row (17*16 -> conflict-free ldmatrix)
#define TILE2_BYTES (128 * RB2)     // 34816
#define CHUNK2 (TILE2_BYTES / 16)   // 2176

// ---------------- static device scratch ----------------
__device__ __half g_zf[16384 * RS2];  // A = [h_z | l_z], padded rows
__device__ __half g_ef[16384 * RS2];  // B = [h_E | l_E], E = 4096*e
__device__ float g_enorm[NE];
__device__ float g_znorm[NT];
__device__ int   g_idx[NT];
__device__ int   g_counts[NE];
__device__ float g_loss;

// ---------------- helpers ----------------
__device__ __forceinline__ uint32_t smem_u32(const void* p) {
    uint32_t a;
    asm("{ .reg .u64 t; cvta.to.shared.u64 t, %1; cvt.u32.u64 %0, t; }" : "=r"(a) : "l"(p));
    return a;
}
__device__ __forceinline__ void split2h(float v, __half& h, __half& l) {
    __half hh = __float2half_rn(v);
    float r = __fsub_rn(v, __half2float(hh));   // exact
    h = hh; l = __float2half_rn(r);
}

#define CP_ASYNC16(dst_u32, src_ptr) \
    asm volatile("cp.async.cg.shared.global [%0], [%1], 16;\n" :: "r"(dst_u32), "l"(src_ptr))
#define CP_COMMIT()  asm volatile("cp.async.commit_group;\n" ::: "memory")
#define CP_WAIT0()   asm volatile("cp.async.wait_group 0;\n" ::: "memory")

#define LDSM_X4(r, addr) \
    asm volatile("ldmatrix.sync.aligned.m8n8.x4.shared.b16 {%0,%1,%2,%3}, [%4];" \
        : "=r"((r)[0]), "=r"((r)[1]), "=r"((r)[2]), "=r"((r)[3]) : "r"(addr))
#define LDSM_X2(r, addr) \
    asm volatile("ldmatrix.sync.aligned.m8n8.x2.shared.b16 {%0,%1}, [%2];" \
        : "=r"((r)[0]), "=r"((r)[1]) : "r"(addr))

__device__ __forceinline__ void mma16816(float* c, const uint32_t* a, const uint32_t* b) {
    asm volatile(
        "mma.sync.aligned.m16n8k16.row.col.f32.f16.f16.f32 "
        "{%0,%1,%2,%3}, {%4,%5,%6,%7}, {%8,%9}, {%0,%1,%2,%3};"
        : "+f"(c[0]), "+f"(c[1]), "+f"(c[2]), "+f"(c[3])
        : "r"(a[0]), "r"(a[1]), "r"(a[2]), "r"(a[3]), "r"(b[0]), "r"(b[1]));
}

// ---------------- prep (fused): split z and E=4096*e; norms; zero counts ----------------
__global__ void k_split(const float* __restrict__ z, const float* __restrict__ emb) {
    extern __shared__ __half st[];          // 128 * RS2 halves = 34816 B
    int blk = blockIdx.x;                   // 0..127 z tiles, 128..255 e subtiles
    int tid = threadIdx.x;                  // 256
    if (blk < 128) {
        int tile = blk;
        int b = tile >> 3, hw0 = (tile & 7) << 7;
        for (int idx = tid; idx < 8192; idx += 256) {
            int k = idx >> 7, tl = idx & 127;
            float v = z[((size_t)(b * 64 + k) << 10) + hw0 + tl];
            __half h, l; split2h(v, h, l);
            st[tl * RS2 + k]      = h;
            st[tl * RS2 + 64 + k] = l;
        }
        __syncthreads();
        float4* dst = (float4*)(g_zf + (size_t)tile * 128 * RS2);
        const float4* src = (const float4*)st;
        for (int i = tid; i < CHUNK2; i += 256) dst[i] = src[i];
        if (tid < 128) {
            float s = 0.f;
            for (int k = 0; k < 64; k++) {
                float v = z[((size_t)(b * 64 + k) << 10) + hw0 + tid];
                s += v * v;
            }
            g_znorm[(tile << 7) + tid] = s;
        }
        if (tile == 0 && tid == 0) g_loss = 0.f;
    } else {
        int sub = blk - 128;
        int n0 = sub << 7;
        for (int idx = tid; idx < 8192; idx += 256) {
            int nl = idx >> 6, k = idx & 63;
            float v = emb[(size_t)(n0 + nl) * 64 + k] * 4096.0f;   // exact scale
            __half h, l; split2h(v, h, l);
            st[nl * RS2 + k]      = h;
            st[nl * RS2 + 64 + k] = l;
        }
        __syncthreads();
        float4* dst = (float4*)(g_ef + (size_t)sub * 128 * RS2);
        const float4* src = (const float4*)st;
        for (int i = tid; i < CHUNK2; i += 256) dst[i] = src[i];
        if (tid < 128) {
            float s = 0.f;
            for (int k = 0; k < 64; k++) {
                float v = emb[(size_t)(n0 + tid) * 64 + k];
                s += v * v;
            }
            g_enorm[n0 + tid] = s;
            g_counts[n0 + tid] = 0;
        }
    }
}

// ---------------- building blocks ----------------
__device__ __forceinline__ void load_en(int j, int nbw, int lane, float en[8]) {
#pragma unroll
    for (int ni = 0; ni < 4; ni++) {
        int c0 = nbw + ni * 8 + (lane & 3) * 2;
        en[ni * 2]     = __ldg(&g_enorm[(j << 7) + c0]);
        en[ni * 2 + 1] = __ldg(&g_enorm[(j << 7) + c0 + 1]);
    }
}

// 3-product (hh + lh + hl) mma over K=128 stored tiles; fragments register-cached.
__device__ __forceinline__ void mma_phase(uint32_t a_base, uint32_t b_base,
                                          float acc[4][4][4]) {
#pragma unroll
    for (int mi = 0; mi < 4; mi++)
#pragma unroll
        for (int ni = 0; ni < 4; ni++)
#pragma unroll
            for (int q = 0; q < 4; q++) acc[mi][ni][q] = 0.f;
#pragma unroll
    for (int ks = 0; ks < 4; ks++) {
        uint32_t ah[4][4], al[4][4], bh[4][2], bl[4][2];
#pragma unroll
        for (int mi = 0; mi < 4; mi++) {
            LDSM_X4(ah[mi], a_base + mi * 16 * RB2 + ks * 32);
            LDSM_X4(al[mi], a_base + mi * 16 * RB2 + 128 + ks * 32);
        }
#pragma unroll
        for (int ni = 0; ni < 4; ni++) {
            LDSM_X2(bh[ni], b_base + ni * 8 * RB2 + ks * 32);
            LDSM_X2(bl[ni], b_base + ni * 8 * RB2 + 128 + ks * 32);
        }
#pragma unroll
        for (int mi = 0; mi < 4; mi++)
#pragma unroll
            for (int ni = 0; ni < 4; ni++)
                mma16816(acc[mi][ni], ah[mi], bh[ni]);
#pragma unroll
        for (int mi = 0; mi < 4; mi++)
#pragma unroll
            for (int ni = 0; ni < 4; ni++)
                mma16816(acc[mi][ni], al[mi], bh[ni]);
#pragma unroll
        for (int mi = 0; mi < 4; mi++)
#pragma unroll
            for (int ni = 0; ni < 4; ni++)
                mma16816(acc[mi][ni], ah[mi], bl[ni]);
    }
}

// d = fl( fl(zn+en) - acc*2^-11 ), single FFMA rounding (acc*2^-11 exact).
__device__ __forceinline__ void epi_phase(const float acc[4][4][4], const float en[8],
                                          const float zn[8], int j, int nbw, int lane,
                                          float bv[8], int bi[8]) {
#pragma unroll
    for (int mi = 0; mi < 4; mi++) {
#pragma unroll
        for (int ni = 0; ni < 4; ni++) {
            int n0 = (j << 7) + nbw + ni * 8 + (lane & 3) * 2;
            float c00 = __fadd_rn(zn[mi * 2],     en[ni * 2]);
            float c01 = __fadd_rn(zn[mi * 2],     en[ni * 2 + 1]);
            float c10 = __fadd_rn(zn[mi * 2 + 1], en[ni * 2]);
            float c11 = __fadd_rn(zn[mi * 2 + 1], en[ni * 2 + 1]);
            float d0 = fmaf(acc[mi][ni][0], -0x1p-11f, c00);
            float d1 = fmaf(acc[mi][ni][1], -0x1p-11f, c01);
            float d2 = fmaf(acc[mi][ni][2], -0x1p-11f, c10);
            float d3 = fmaf(acc[mi][ni][3], -0x1p-11f, c11);
            if (d0 < bv[mi * 2])     { bv[mi * 2]     = d0; bi[mi * 2]     = n0; }
            if (d1 < bv[mi * 2])     { bv[mi * 2]     = d1; bi[mi * 2]     = n0 + 1; }
            if (d2 < bv[mi * 2 + 1]) { bv[mi * 2 + 1] = d2; bi[mi * 2 + 1] = n0; }
            if (d3 < bv[mi * 2 + 1]) { bv[mi * 2 + 1] = d3; bi[mi * 2 + 1] = n0 + 1; }
        }
    }
}

// ---------------- main: fp16 mma.sync distance GEMM + fused argmin ----------------
// smem: A [0,34816) | B0 [34816,69632) | B1 [69632,104448)
#define SM_TOT (3 * TILE2_BYTES)

__global__ void __launch_bounds__(256, 1) k_mma(float* __restrict__ out) {
    extern __shared__ __align__(16) unsigned char sm[];
    uint32_t sb = smem_u32(sm);
    const uint32_t SA = sb, SB0 = sb + TILE2_BYTES, SB1 = sb + 2 * TILE2_BYTES;

    int tid = threadIdx.x, lane = tid & 31, wid = tid >> 5;
    int mw = wid & 1, nw = wid >> 1;        // 2 x 4 warp grid
    int mbase = mw * 64, nbw = nw * 32;     // warp tile 64 x 32

    // prolog: A tile + B subtile 0
    {
        const char* gz = (const char*)(g_zf + (size_t)blockIdx.x * 128 * RS2);
        for (int i = tid; i < CHUNK2; i += 256) CP_ASYNC16(SA + i * 16, gz + i * 16);
        const char* ge = (const char*)g_ef;
        for (int i = tid; i < CHUNK2; i += 256) CP_ASYNC16(SB0 + i * 16, ge + i * 16);
        CP_COMMIT(); CP_WAIT0();
    }
    __syncthreads();

    // per-thread rows: r = mbase + mi*16 + rh*8 + (lane>>2)
    float zn[8];
#pragma unroll
    for (int mi = 0; mi < 4; mi++)
#pragma unroll
        for (int rh = 0; rh < 2; rh++)
            zn[mi * 2 + rh] = g_znorm[(blockIdx.x << 7) + mbase + mi * 16 + rh * 8 + (lane >> 2)];

    float bv[8]; int bi[8];
#pragma unroll
    for (int r = 0; r < 8; r++) { bv[r] = 3.0e38f; bi[r] = 0; }

    // ldmatrix base addresses (conflict-free with 272B row stride)
    uint32_t a_base = SA + (uint32_t)(mbase + (lane & 15)) * RB2 + ((lane >> 4) & 1) * 16;
    uint32_t b_roff = (uint32_t)(nbw + (lane & 7)) * RB2 + ((lane >> 3) & 1) * 16;

    float acc[4][4][4];

    for (int j = 0; j < 128; j++) {
        int cur = j & 1;
        uint32_t Bcur  = cur ? SB1 : SB0;
        uint32_t Bnext = cur ? SB0 : SB1;

        if (j < 127) {   // prefetch next B, overlapped with this subtile's mma
            const char* src = (const char*)(g_ef + (size_t)(j + 1) * 128 * RS2);
            for (int i = tid; i < CHUNK2; i += 256) CP_ASYNC16(Bnext + i * 16, src + i * 16);
            CP_COMMIT();
        }

        float en[8];
        load_en(j, nbw, lane, en);

        mma_phase(a_base, Bcur + b_roff, acc);
        epi_phase(acc, en, zn, j, nbw, lane, bv, bi);

        CP_WAIT0();
        __syncthreads();
    }

    // quad reduce (cols within warp): lanes differing in (lane&3)
#pragma unroll
    for (int r = 0; r < 8; r++) {
#pragma unroll
        for (int off = 1; off <= 2; off <<= 1) {
            float ov = __shfl_xor_sync(0xffffffffu, bv[r], off);
            int   oi = __shfl_xor_sync(0xffffffffu, bi[r], off);
            if (ov < bv[r] || (ov == bv[r] && oi < bi[r])) { bv[r] = ov; bi[r] = oi; }
        }
    }
    __syncthreads();
    float* rv = (float*)(sm + TILE2_BYTES);          // reuse B0: 128 rows x 4 nwarps
    int*   ri = (int*)(sm + TILE2_BYTES + 2048);
    if ((lane & 3) == 0) {
#pragma unroll
        for (int r = 0; r < 8; r++) {
            int row = mbase + (r >> 1) * 16 + (r & 1) * 8 + (lane >> 2);
            rv[row * 4 + nw] = bv[r];
            ri[row * 4 + nw] = bi[r];
        }
    }
    __syncthreads();
    if (tid < 128) {
        float v = rv[tid * 4]; int ii = ri[tid * 4];
#pragma unroll
        for (int x = 1; x < 4; x++) {
            float ov = rv[tid * 4 + x]; int oi = ri[tid * 4 + x];
            if (ov < v || (ov == v && oi < ii)) { v = ov; ii = oi; }
        }
        int t = (blockIdx.x << 7) + tid;
        g_idx[t] = ii;
        out[1048579 + t] = (float)ii;
        atomicAdd(&g_counts[ii], 1);
    }
}

// ---------------- z_q gather + loss accumulation ----------------
__global__ void k_zq(const float* __restrict__ z, const float* __restrict__ emb,
                     float* __restrict__ out) {
    int p = blockIdx.x;            // 1024 planes = (b,c)
    int b = p >> 6, c = p & 63;
    int tid = threadIdx.x;         // 256
    float ls = 0.f;
    for (int hw = tid; hw < 1024; hw += 256) {
        int t = (b << 10) + hw;
        int id = g_idx[t];
        float v  = emb[(size_t)id * 64 + c];
        float zv = z[(size_t)p * 1024 + hw];
        out[(size_t)p * 1024 + hw] = v;
        float df = v - zv;
        ls += df * df;
    }
    __shared__ float red[8];
    for (int o = 16; o > 0; o >>= 1) ls += __shfl_down_sync(0xffffffff, ls, o);
    if ((tid & 31) == 0) red[tid >> 5] = ls;
    __syncthreads();
    if (tid == 0) {
        float s = 0.f;
        for (int w = 0; w < 8; w++) s += red[w];
        atomicAdd(&g_loss, s);
    }
}

// ---------------- scalars ----------------
__global__ void k_final(float* __restrict__ out) {
    int tid = threadIdx.x;   // 1024
    float ent = 0.f; int cu = 0;
    for (int n = tid; n < NE; n += 1024) {
        int c = g_counts[n];
        if (c > 0) cu++;
        float avg = (float)c * (1.0f / 16384.0f);
        ent += avg * logf(avg + 1e-10f);
    }
    __shared__ float se[1024]; __shared__ int sc[1024];
    se[tid] = ent; sc[tid] = cu;
    __syncthreads();
    for (int o = 512; o > 0; o >>= 1) {
        if (tid < o) { se[tid] += se[tid + o]; sc[tid] += sc[tid + o]; }
        __syncthreads();
    }
    if (tid == 0) {
        out[1048576] = g_loss * (1.0f + BETA) / 1048576.0f;
        out[1048577] = expf(-se[0]);
        out[1048578] = (float)sc[0];
    }
}

// ---------------- launch ----------------
extern "C" void kernel_launch(void* const* d_in, const int* in_sizes, int n_in,
                              void* d_out, int out_size) {
    const float* z   = (const float*)d_in[0];   // (16,64,32,32)
    const float* emb = (const float*)d_in[1];   // (16384,64)
    float* out = (float*)d_out;

    cudaFuncSetAttribute(k_split, cudaFuncAttributeMaxDynamicSharedMemorySize, TILE2_BYTES);
    cudaFuncSetAttribute(k_mma,   cudaFuncAttributeMaxDynamicSharedMemorySize, SM_TOT);

    k_split<<<256, 256, TILE2_BYTES>>>(z, emb);
    k_mma<<<128, 256, SM_TOT>>>(out);
    k_zq<<<1024, 256>>>(z, emb, out);
    k_final<<<1, 1024>>>(out);
}